// round 2
// baseline (speedup 1.0000x reference)
#include <cuda_runtime.h>
#include <cstdint>
#include <cstddef>

#define S_TOK 65536
#define HDIM 768
#define TT 6
#define KK 3
#define WIN 15
#define GRID1 152
#define NTHREAD 256
#define NWARP 8
#define GROUPS (S_TOK/4)

// ---- scratch (no allocations allowed) ----
__device__ float g_end [TT*S_TOK];      // end scores, [t][s]
__device__ float g_pool[GRID1*HDIM];    // per-block pooled partial sums
__device__ float g_m  [GRID1*TT];       // per-block max of start scores
__device__ float g_z  [GRID1*TT];       // per-block sum exp(x - m)
__device__ float g_t3v[GRID1*TT*3];     // per-block top3 values
__device__ int   g_t3i[GRID1*TT*3];     // per-block top3 indices

__device__ __forceinline__ void fma2(unsigned long long &d, unsigned long long a, unsigned long long b){
    asm("fma.rn.f32x2 %0, %1, %2, %0;" : "+l"(d) : "l"(a), "l"(b));
}
__device__ __forceinline__ void add2(unsigned long long &d, unsigned long long a){
    asm("add.rn.f32x2 %0, %0, %1;" : "+l"(d) : "l"(a));
}
__device__ __forceinline__ float2 up2(unsigned long long u){
    float2 r;
    r.x = __uint_as_float((unsigned)(u & 0xffffffffull));
    r.y = __uint_as_float((unsigned)(u >> 32));
    return r;
}
__device__ __forceinline__ bool better(float v, int i, float V, int I){
    return (v > V) || (v == V && i < I);
}

__global__ __launch_bounds__(NTHREAD,1) void k1(
    const float* __restrict__ emb, const float* __restrict__ Wst,
    const float* __restrict__ bst, const float* __restrict__ Wen,
    const float* __restrict__ ben)
{
    __shared__ __align__(16) float sW[12*HDIM];   // [0..6): W_start^T, [6..12): W_end^T ; reused for pooled later
    __shared__ float sM[NWARP][TT], sZ[NWARP][TT];
    __shared__ float sT3v[NWARP][TT][3];
    __shared__ int   sT3i[NWARP][TT][3];

    const int tid = threadIdx.x, w = tid >> 5, lane = tid & 31;

    // load weights transposed: sW[t*768+h] = W[h*6+t]
    for(int i = tid; i < HDIM*TT; i += NTHREAD){
        int h = i / TT, t = i - h*TT;
        sW[t*HDIM + h]        = Wst[i];
        sW[(TT+t)*HDIM + h]   = Wen[i];
    }
    __syncthreads();

    unsigned long long pool[12];
    #pragma unroll
    for(int i = 0; i < 12; i++) pool[i] = 0ull;

    float mv = -3.4e38f, zv = 0.f;                 // online logsumexp (lane t owns type t)
    float v0 = -3.4e38f, v1 = -3.4e38f, v2 = -3.4e38f;
    int   i0 = 0x7fffffff, i1 = 0x7fffffff, i2 = 0x7fffffff;
    const float bsl = (lane < TT) ? bst[lane] : 0.f;
    const float bel = (lane < TT) ? ben[lane] : 0.f;

    const int gw = blockIdx.x * NWARP + w;
    const int nw = GRID1 * NWARP;

    for(int g = gw; g < GROUPS; g += nw){
        const int r0 = g * 4;
        unsigned long long acc[4][12];
        #pragma unroll
        for(int r = 0; r < 4; r++)
            #pragma unroll
            for(int d = 0; d < 12; d++) acc[r][d] = 0ull;

        const float* base = emb + (size_t)r0 * HDIM + (lane << 2);
        #pragma unroll
        for(int j = 0; j < 6; j++){
            const int off = j * 128;
            ulonglong2 A0 = *reinterpret_cast<const ulonglong2*>(base + off);
            ulonglong2 A1 = *reinterpret_cast<const ulonglong2*>(base + HDIM   + off);
            ulonglong2 A2 = *reinterpret_cast<const ulonglong2*>(base + 2*HDIM + off);
            ulonglong2 A3 = *reinterpret_cast<const ulonglong2*>(base + 3*HDIM + off);

            add2(pool[2*j],   A0.x); add2(pool[2*j],   A1.x); add2(pool[2*j],   A2.x); add2(pool[2*j],   A3.x);
            add2(pool[2*j+1], A0.y); add2(pool[2*j+1], A1.y); add2(pool[2*j+1], A2.y); add2(pool[2*j+1], A3.y);

            const float* wp = sW + off + (lane << 2);
            #pragma unroll
            for(int d = 0; d < 12; d++){
                ulonglong2 Wv = *reinterpret_cast<const ulonglong2*>(wp + d*HDIM);
                fma2(acc[0][d], A0.x, Wv.x); fma2(acc[0][d], A0.y, Wv.y);
                fma2(acc[1][d], A1.x, Wv.x); fma2(acc[1][d], A1.y, Wv.y);
                fma2(acc[2][d], A2.x, Wv.x); fma2(acc[2][d], A2.y, Wv.y);
                fma2(acc[3][d], A3.x, Wv.x); fma2(acc[3][d], A3.y, Wv.y);
            }
        }

        #pragma unroll
        for(int r = 0; r < 4; r++){
            float svm = 0.f, evm = 0.f;
            #pragma unroll
            for(int d = 0; d < 12; d++){
                float2 p = up2(acc[r][d]);
                float v = p.x + p.y;
                #pragma unroll
                for(int o = 16; o > 0; o >>= 1) v += __shfl_xor_sync(0xffffffffu, v, o);
                if(d < TT){ if(lane == d)      svm = v; }
                else      { if(lane == d - TT) evm = v; }
            }
            if(lane < TT){
                const int idx = r0 + r;
                g_end[lane*S_TOK + idx] = evm + bel;
                float x = svm + bsl;
                if(x > mv){ zv = zv * __expf(mv - x) + 1.f; mv = x; }
                else      { zv += __expf(x - mv); }
                if     (better(x, idx, v0, i0)){ v2=v1; i2=i1; v1=v0; i1=i0; v0=x; i0=idx; }
                else if(better(x, idx, v1, i1)){ v2=v1; i2=i1; v1=x;  i1=idx; }
                else if(better(x, idx, v2, i2)){ v2=x;  i2=idx; }
            }
        }
    }

    if(lane < TT){
        sM[w][lane] = mv; sZ[w][lane] = zv;
        sT3v[w][lane][0] = v0; sT3v[w][lane][1] = v1; sT3v[w][lane][2] = v2;
        sT3i[w][lane][0] = i0; sT3i[w][lane][1] = i1; sT3i[w][lane][2] = i2;
    }
    __syncthreads();   // all warps done with weights -> reuse sW for pooled partials

    float* sP = sW;
    #pragma unroll
    for(int j = 0; j < 6; j++){
        ulonglong2 u; u.x = pool[2*j]; u.y = pool[2*j+1];
        *reinterpret_cast<ulonglong2*>(sP + w*HDIM + j*128 + (lane << 2)) = u;
    }
    __syncthreads();

    for(int h = tid; h < HDIM; h += NTHREAD){
        float s = 0.f;
        #pragma unroll
        for(int ww = 0; ww < NWARP; ww++) s += sP[ww*HDIM + h];
        g_pool[blockIdx.x*HDIM + h] = s;
    }

    if(tid < TT){
        float M = -3.4e38f;
        for(int ww = 0; ww < NWARP; ww++) M = fmaxf(M, sM[ww][tid]);
        float Z = 0.f;
        for(int ww = 0; ww < NWARP; ww++) Z += sZ[ww][tid] * __expf(sM[ww][tid] - M);
        g_m[blockIdx.x*TT + tid] = M;
        g_z[blockIdx.x*TT + tid] = Z;

        float V0=-3.4e38f, V1=-3.4e38f, V2=-3.4e38f;
        int   I0=0x7fffffff, I1=0x7fffffff, I2=0x7fffffff;
        for(int ww = 0; ww < NWARP; ww++){
            #pragma unroll
            for(int k = 0; k < 3; k++){
                float x = sT3v[ww][tid][k]; int idx = sT3i[ww][tid][k];
                if     (better(x, idx, V0, I0)){ V2=V1; I2=I1; V1=V0; I1=I0; V0=x; I0=idx; }
                else if(better(x, idx, V1, I1)){ V2=V1; I2=I1; V1=x;  I1=idx; }
                else if(better(x, idx, V2, I2)){ V2=x;  I2=idx; }
            }
        }
        const int bo = (blockIdx.x*TT + tid) * 3;
        g_t3v[bo+0]=V0; g_t3v[bo+1]=V1; g_t3v[bo+2]=V2;
        g_t3i[bo+0]=I0; g_t3i[bo+1]=I1; g_t3i[bo+2]=I2;
    }
}

__global__ void k2(const float* __restrict__ W1, const float* __restrict__ b1,
                   const float* __restrict__ W2, const float* __restrict__ b2,
                   float* __restrict__ out, int out_size)
{
    __shared__ float pooled[HDIM];
    __shared__ float hbuf[64];
    __shared__ float tc[TT], Mt[TT], Zt[TT];
    __shared__ float t3v[TT][3];
    __shared__ int   t3i[TT][3];
    const int tid = threadIdx.x;

    for(int i = tid; i < out_size; i += NTHREAD) out[i] = 0.f;

    if(tid < 192){
        float4 a = make_float4(0.f,0.f,0.f,0.f);
        for(int b = 0; b < GRID1; b++){
            float4 v = *reinterpret_cast<const float4*>(&g_pool[b*HDIM + tid*4]);
            a.x += v.x; a.y += v.y; a.z += v.z; a.w += v.w;
        }
        const float inv = 1.f / (float)S_TOK;
        pooled[tid*4+0] = a.x*inv; pooled[tid*4+1] = a.y*inv;
        pooled[tid*4+2] = a.z*inv; pooled[tid*4+3] = a.w*inv;
    } else if(tid < 192 + TT){
        const int t = tid - 192;
        float M = -3.4e38f;
        for(int b = 0; b < GRID1; b++) M = fmaxf(M, g_m[b*TT + t]);
        float Z = 0.f;
        for(int b = 0; b < GRID1; b++) Z += g_z[b*TT + t] * __expf(g_m[b*TT + t] - M);
        Mt[t] = M; Zt[t] = Z;

        float V0=-3.4e38f, V1=-3.4e38f, V2=-3.4e38f;
        int   I0=0x7fffffff, I1=0x7fffffff, I2=0x7fffffff;
        for(int b = 0; b < GRID1; b++){
            #pragma unroll
            for(int k = 0; k < 3; k++){
                float x = g_t3v[(b*TT+t)*3 + k]; int idx = g_t3i[(b*TT+t)*3 + k];
                if     (better(x, idx, V0, I0)){ V2=V1; I2=I1; V1=V0; I1=I0; V0=x; I0=idx; }
                else if(better(x, idx, V1, I1)){ V2=V1; I2=I1; V1=x;  I1=idx; }
                else if(better(x, idx, V2, I2)){ V2=x;  I2=idx; }
            }
        }
        t3v[t][0]=V0; t3v[t][1]=V1; t3v[t][2]=V2;
        t3i[t][0]=I0; t3i[t][1]=I1; t3i[t][2]=I2;
    }
    __syncthreads();

    if(tid < 64){
        float a = b1[tid];
        for(int h = 0; h < HDIM; h++) a += pooled[h] * W1[h*64 + tid];
        hbuf[tid] = 0.5f * a * (1.f + erff(a * 0.70710678118654752f));  // exact gelu
    }
    __syncthreads();
    if(tid < TT){
        float z = b2[tid];
        for(int j = 0; j < 64; j++) z += hbuf[j] * W2[j*TT + tid];
        tc[tid] = 1.f / (1.f + expf(-z));
    }
    __syncthreads();

    if(tid < TT*KK){
        const int t = tid / KK, k = tid - t*KK;
        const int idx = t3i[t][k];
        const float pv = expf(t3v[t][k] - Mt[t]) / Zt[t];

        float best = -3.4e38f; int off = 0;
        #pragma unroll
        for(int ww = 0; ww < WIN; ww++){
            int pos = idx + ww;
            if(pos < S_TOK){
                float v = g_end[t*S_TOK + pos];
                if(v > best){ best = v; off = ww; }
            }
        }
        const bool valid = (tc[t] >= 0.3f) && (pv >= 0.15f);
        const float c = valid ? pv * tc[t] : 0.f;
        const int base = t*KK + k;
        if(base      < out_size) out[base]      = c;
        if(18 + base < out_size) out[18 + base] = (float)idx;
        if(36 + base < out_size) out[36 + base] = (float)(idx + off + 1);
        if(54 + base < out_size) out[54 + base] = valid ? 1.f : 0.f;
    }
}

extern "C" void kernel_launch(void* const* d_in, const int* in_sizes, int n_in,
                              void* d_out, int out_size)
{
    const float* emb = (const float*)d_in[0];
    const float* Wst = (const float*)d_in[1];
    const float* bst = (const float*)d_in[2];
    const float* Wen = (const float*)d_in[3];
    const float* ben = (const float*)d_in[4];
    const float* W1  = (const float*)d_in[5];
    const float* b1  = (const float*)d_in[6];
    const float* W2  = (const float*)d_in[7];
    const float* b2  = (const float*)d_in[8];

    k1<<<GRID1, NTHREAD>>>(emb, Wst, bst, Wen, ben);
    k2<<<1, NTHREAD>>>(W1, b1, W2, b2, (float*)d_out, out_size);
}

// round 3
// speedup vs baseline: 2.6952x; 2.6952x over previous
#include <cuda_runtime.h>
#include <cstdint>
#include <cstddef>

#define S_TOK 65536
#define HDIM 768
#define TT 6
#define KK 3
#define WIN 15
#define GRID1 152
#define NTHREAD 256
#define NWARP 8
#define GROUPS (S_TOK/4)

// ---- static scratch ----
__device__ float g_end [S_TOK*8];       // end scores, [s][t] padded to 8
__device__ float g_pool[GRID1*HDIM];    // per-block pooled partials
__device__ float g_z  [GRID1*TT];       // per-block sum exp(x)
__device__ float g_t3v[GRID1*TT*3];
__device__ int   g_t3i[GRID1*TT*3];

__device__ __forceinline__ void fma2(unsigned long long &d, unsigned long long a, unsigned long long b){
    asm("fma.rn.f32x2 %0, %1, %2, %0;" : "+l"(d) : "l"(a), "l"(b));
}
__device__ __forceinline__ void add2(unsigned long long &d, unsigned long long a){
    asm("add.rn.f32x2 %0, %0, %1;" : "+l"(d) : "l"(a));
}
__device__ __forceinline__ float lo2(unsigned long long u){ return __uint_as_float((unsigned)(u & 0xffffffffull)); }
__device__ __forceinline__ float hi2(unsigned long long u){ return __uint_as_float((unsigned)(u >> 32)); }
__device__ __forceinline__ bool better(float v,int i,float V,int I){ return (v>V)||(v==V && i<I); }

__global__ __launch_bounds__(NTHREAD,1) void k1(
    const float* __restrict__ emb, const float* __restrict__ Wst,
    const float* __restrict__ Wen)
{
    __shared__ __align__(16) float sW[12*HDIM];   // [0..6) start dims, [6..12) end dims; reused for pool later
    __shared__ float sbuf[NWARP][24];
    __shared__ float sZ[NWARP][TT];
    __shared__ float sT3v[NWARP][TT][3];
    __shared__ int   sT3i[NWARP][TT][3];

    const int tid = threadIdx.x, w = tid>>5, lane = tid&31;

    for(int i=tid;i<HDIM*TT;i+=NTHREAD){
        int h=i/TT, t=i-h*TT;
        sW[t*HDIM+h]      = Wst[i];
        sW[(TT+t)*HDIM+h] = Wen[i];
    }
    __syncthreads();

    unsigned long long pool[12];
    #pragma unroll
    for(int i=0;i<12;i++) pool[i]=0ull;
    float zv=0.f;
    float v0=-3.4e38f,v1=-3.4e38f,v2=-3.4e38f;
    int i0=0x7fffffff,i1=0x7fffffff,i2=0x7fffffff;

    const int b4=(lane>>4)&1, b3=(lane>>3)&1, b2=(lane>>2)&1, b1=(lane>>1)&1, b0=lane&1;
    const int rowown = b4*2+b3;                 // which row this lane owns after reduction
    const int down   = b2*6 + b1*3 + (b0?2:0);  // first owned dim (0..11)

    const int gw = blockIdx.x*NWARP + w;
    const int nw = GRID1*NWARP;

    // prefetch first group's j=0 chunk
    const float* bp0 = emb + (size_t)gw*(4*HDIM) + (lane<<2);
    ulonglong2 C0 = *(const ulonglong2*)(bp0);
    ulonglong2 C1 = *(const ulonglong2*)(bp0+HDIM);
    ulonglong2 C2 = *(const ulonglong2*)(bp0+2*HDIM);
    ulonglong2 C3 = *(const ulonglong2*)(bp0+3*HDIM);

    for(int g=gw; g<GROUPS; g+=nw){
        const int r0=g*4;
        const float* cb = emb + (size_t)g*(4*HDIM) + (lane<<2);
        const int gn = (g+nw<GROUPS)? g+nw : g;
        const float* nb0 = emb + (size_t)gn*(4*HDIM) + (lane<<2);

        unsigned long long a[48];
        #pragma unroll
        for(int i=0;i<48;i++) a[i]=0ull;

        #pragma unroll
        for(int j=0;j<6;j++){
            const float* np = (j<5)? (cb + (j+1)*128) : nb0;
            ulonglong2 N0=*(const ulonglong2*)(np);
            ulonglong2 N1=*(const ulonglong2*)(np+HDIM);
            ulonglong2 N2=*(const ulonglong2*)(np+2*HDIM);
            ulonglong2 N3=*(const ulonglong2*)(np+3*HDIM);

            add2(pool[2*j],  C0.x); add2(pool[2*j],  C1.x); add2(pool[2*j],  C2.x); add2(pool[2*j],  C3.x);
            add2(pool[2*j+1],C0.y); add2(pool[2*j+1],C1.y); add2(pool[2*j+1],C2.y); add2(pool[2*j+1],C3.y);

            const float* wp = sW + j*128 + (lane<<2);
            #pragma unroll
            for(int d=0;d<12;d++){
                ulonglong2 Wv=*(const ulonglong2*)(wp + d*HDIM);
                fma2(a[d],    C0.x,Wv.x); fma2(a[d],    C0.y,Wv.y);
                fma2(a[12+d], C1.x,Wv.x); fma2(a[12+d], C1.y,Wv.y);
                fma2(a[24+d], C2.x,Wv.x); fma2(a[24+d], C2.y,Wv.y);
                fma2(a[36+d], C3.x,Wv.x); fma2(a[36+d], C3.y,Wv.y);
            }
            C0=N0; C1=N1; C2=N2; C3=N3;
        }

        // collapse f32x2 halves
        float v[48];
        #pragma unroll
        for(int i=0;i<48;i++) v[i]=lo2(a[i])+hi2(a[i]);

        // ragged butterfly: 48 -> 24 -> 12 -> 6 -> 3 -> {2,1}
        #pragma unroll
        for(int i=0;i<24;i++){ float s=b4? v[i]:v[i+24]; float r=__shfl_xor_sync(0xffffffffu,s,16); v[i]=(b4? v[i+24]:v[i])+r; }
        #pragma unroll
        for(int i=0;i<12;i++){ float s=b3? v[i]:v[i+12]; float r=__shfl_xor_sync(0xffffffffu,s,8);  v[i]=(b3? v[i+12]:v[i])+r; }
        #pragma unroll
        for(int i=0;i<6;i++){  float s=b2? v[i]:v[i+6];  float r=__shfl_xor_sync(0xffffffffu,s,4);  v[i]=(b2? v[i+6]:v[i])+r; }
        #pragma unroll
        for(int i=0;i<3;i++){  float s=b1? v[i]:v[i+3];  float r=__shfl_xor_sync(0xffffffffu,s,2);  v[i]=(b1? v[i+3]:v[i])+r; }
        {
            float s =b0? v[0]:v[2]; float r =__shfl_xor_sync(0xffffffffu,s,1);
            float s2=v[1];          float r2=__shfl_xor_sync(0xffffffffu,s2,1);
            v[0]=(b0? v[2]:v[0])+r;
            v[1]=v[1]+r2;            // only meaningful for b0==0
        }

        // write out: start dims -> per-warp smem handoff; end dims -> g_end[s][t]
        if(down<6){
            sbuf[w][rowown*6+down]=v[0];
            if(!b0) sbuf[w][rowown*6+down+1]=v[1];
        } else {
            const int s=r0+rowown;
            g_end[s*8+(down-6)]=v[0];
            if(!b0) g_end[s*8+(down-5)]=v[1];
        }
        __syncwarp();
        if(lane<TT){
            #pragma unroll
            for(int r=0;r<4;r++){
                float x=sbuf[w][r*6+lane];
                zv += __expf(x);
                const int idx=r0+r;
                if     (better(x,idx,v0,i0)){ v2=v1;i2=i1; v1=v0;i1=i0; v0=x;i0=idx; }
                else if(better(x,idx,v1,i1)){ v2=v1;i2=i1; v1=x; i1=idx; }
                else if(better(x,idx,v2,i2)){ v2=x; i2=idx; }
            }
        }
        __syncwarp();
    }

    if(lane<TT){
        sZ[w][lane]=zv;
        sT3v[w][lane][0]=v0; sT3v[w][lane][1]=v1; sT3v[w][lane][2]=v2;
        sT3i[w][lane][0]=i0; sT3i[w][lane][1]=i1; sT3i[w][lane][2]=i2;
    }
    __syncthreads();            // weights no longer needed -> reuse sW
    float* sP = sW;
    #pragma unroll
    for(int j=0;j<6;j++){
        ulonglong2 u; u.x=pool[2*j]; u.y=pool[2*j+1];
        *reinterpret_cast<ulonglong2*>(sP + w*HDIM + j*128 + (lane<<2)) = u;
    }
    __syncthreads();

    for(int h=tid;h<HDIM;h+=NTHREAD){
        float s=0.f;
        #pragma unroll
        for(int ww=0;ww<NWARP;ww++) s+=sP[ww*HDIM+h];
        g_pool[blockIdx.x*HDIM+h]=s;
    }

    if(tid<TT){
        float Z=0.f;
        #pragma unroll
        for(int ww=0;ww<NWARP;ww++) Z+=sZ[ww][tid];
        g_z[blockIdx.x*TT+tid]=Z;

        float V0=-3.4e38f,V1=-3.4e38f,V2=-3.4e38f;
        int   I0=0x7fffffff,I1=0x7fffffff,I2=0x7fffffff;
        #pragma unroll
        for(int ww=0;ww<NWARP;ww++){
            #pragma unroll
            for(int k=0;k<3;k++){
                float x=sT3v[ww][tid][k]; int idx=sT3i[ww][tid][k];
                if     (better(x,idx,V0,I0)){ V2=V1;I2=I1; V1=V0;I1=I0; V0=x;I0=idx; }
                else if(better(x,idx,V1,I1)){ V2=V1;I2=I1; V1=x; I1=idx; }
                else if(better(x,idx,V2,I2)){ V2=x; I2=idx; }
            }
        }
        const int bo=(blockIdx.x*TT+tid)*3;
        g_t3v[bo  ]=V0; g_t3v[bo+1]=V1; g_t3v[bo+2]=V2;
        g_t3i[bo  ]=I0; g_t3i[bo+1]=I1; g_t3i[bo+2]=I2;
    }
}

#define INS3(x,id) do{ \
    if     (better((x),(id),m0,j0)){ m2=m1;j2=j1; m1=m0;j1=j0; m0=(x);j0=(id); } \
    else if(better((x),(id),m1,j1)){ m2=m1;j2=j1; m1=(x);j1=(id); } \
    else if(better((x),(id),m2,j2)){ m2=(x);j2=(id); } }while(0)

__global__ __launch_bounds__(NTHREAD) void k2(
    const float* __restrict__ W1, const float* __restrict__ b1,
    const float* __restrict__ W2, const float* __restrict__ b2,
    float* __restrict__ out, int out_size)
{
    __shared__ float pooled[HDIM];
    __shared__ float red[NTHREAD];
    __shared__ float hbuf[64];
    __shared__ float tc[TT], fZ[TT], fV[TT][3];
    __shared__ int   fI[TT][3];

    const int tid=threadIdx.x, w=tid>>5, lane=tid&31;

    // ---- parallel per-type merge: one warp per type ----
    if(w<TT){
        const int t=w;
        float Z=0.f;
        float m0=-3.4e38f,m1=-3.4e38f,m2=-3.4e38f;
        int   j0=0x7fffffff,j1=0x7fffffff,j2=0x7fffffff;
        for(int b=lane;b<GRID1;b+=32){
            Z += g_z[b*TT+t];
            #pragma unroll
            for(int k=0;k<3;k++){
                float x=g_t3v[(b*TT+t)*3+k]; int id=g_t3i[(b*TT+t)*3+k];
                INS3(x,id);
            }
        }
        #pragma unroll
        for(int off=16;off>0;off>>=1){
            Z += __shfl_xor_sync(0xffffffffu,Z,off);
            float u0=__shfl_xor_sync(0xffffffffu,m0,off); int q0=__shfl_xor_sync(0xffffffffu,j0,off);
            float u1=__shfl_xor_sync(0xffffffffu,m1,off); int q1=__shfl_xor_sync(0xffffffffu,j1,off);
            float u2=__shfl_xor_sync(0xffffffffu,m2,off); int q2=__shfl_xor_sync(0xffffffffu,j2,off);
            INS3(u0,q0); INS3(u1,q1); INS3(u2,q2);
        }
        if(lane==0){
            fZ[t]=Z;
            fV[t][0]=m0; fV[t][1]=m1; fV[t][2]=m2;
            fI[t][0]=j0; fI[t][1]=j1; fI[t][2]=j2;
        }
    }
    __syncthreads();

    // ---- pooled sum (192 threads, float4) ----
    if(tid<192){
        float4 a=make_float4(0.f,0.f,0.f,0.f);
        #pragma unroll 4
        for(int b=0;b<GRID1;b++){
            const float4 u=*reinterpret_cast<const float4*>(&g_pool[b*HDIM+tid*4]);
            a.x+=u.x; a.y+=u.y; a.z+=u.z; a.w+=u.w;
        }
        const float inv=1.f/(float)S_TOK;
        pooled[tid*4+0]=a.x*inv; pooled[tid*4+1]=a.y*inv;
        pooled[tid*4+2]=a.z*inv; pooled[tid*4+3]=a.w*inv;
    }
    __syncthreads();

    // ---- W1 GEMV split 4 ways across 256 threads ----
    {
        const int u=tid&63, sl=tid>>6;
        float acc=0.f;
        const int h0=sl*192;
        #pragma unroll 4
        for(int h=h0;h<h0+192;h++) acc += pooled[h]*W1[h*64+u];
        red[tid]=acc;
    }
    __syncthreads();
    if(tid<64){
        float aa=red[tid]+red[tid+64]+red[tid+128]+red[tid+192]+b1[tid];
        hbuf[tid]=0.5f*aa*(1.f+erff(aa*0.70710678118654752f));
    }
    __syncthreads();
    if(tid<TT){
        float z=b2[tid];
        #pragma unroll
        for(int j=0;j<64;j++) z+=hbuf[j]*W2[j*TT+tid];
        tc[tid]=1.f/(1.f+expf(-z));
    }
    __syncthreads();

    // ---- windows + outputs ----
    if(tid<TT*KK){
        const int t=tid/KK, k=tid-t*KK;
        const int idx=fI[t][k];
        const float p=__expf(fV[t][k])/fZ[t];

        float best=-3.4e38f; int off=0;
        #pragma unroll
        for(int wv=0;wv<WIN;wv++){
            int pos=idx+wv;
            if(pos<S_TOK){
                float e=g_end[pos*8+t];
                if(e>best){ best=e; off=wv; }
            }
        }
        const bool valid=(tc[t]>=0.3f)&&(p>=0.15f);
        const float c=valid? p*tc[t] : 0.f;
        const int base=t*KK+k;
        if(base      < out_size) out[base]      = c;
        if(18+base   < out_size) out[18+base]   = (float)idx;
        if(36+base   < out_size) out[36+base]   = (float)(idx+off+1);
        if(54+base   < out_size) out[54+base]   = valid? 1.f:0.f;
    }
}

extern "C" void kernel_launch(void* const* d_in, const int* in_sizes, int n_in,
                              void* d_out, int out_size)
{
    const float* emb = (const float*)d_in[0];
    const float* Wst = (const float*)d_in[1];
    const float* Wen = (const float*)d_in[3];
    const float* W1  = (const float*)d_in[5];
    const float* b1  = (const float*)d_in[6];
    const float* W2  = (const float*)d_in[7];
    const float* b2  = (const float*)d_in[8];

    k1<<<GRID1, NTHREAD>>>(emb, Wst, Wen);
    k2<<<1, NTHREAD>>>(W1, b1, W2, b2, (float*)d_out, out_size);
}

// round 4
// speedup vs baseline: 3.7176x; 1.3794x over previous
#include <cuda_runtime.h>
#include <cstdint>
#include <cstddef>

#define S_TOK 65536
#define HDIM 768
#define TT 6
#define KK 3
#define WIN 15
#define GRID1 152
#define NTHREAD 256
#define NWARP 8
#define GROUPS (S_TOK/4)
#define GRID2A 64

// ---- static scratch ----
__device__ float g_end [S_TOK*8];       // end scores, [s][t] padded to 8
__device__ float g_pool[GRID1*HDIM];    // per-block pooled partials
__device__ float g_z  [GRID1*TT];       // per-block sum exp(x)
__device__ float g_t3v[GRID1*TT*3];
__device__ int   g_t3i[GRID1*TT*3];
__device__ float g_y  [GRID2A*64];      // W1 GEMV partials

__device__ __forceinline__ void fma2(unsigned long long &d, unsigned long long a, unsigned long long b){
    asm("fma.rn.f32x2 %0, %1, %2, %0;" : "+l"(d) : "l"(a), "l"(b));
}
__device__ __forceinline__ void add2(unsigned long long &d, unsigned long long a){
    asm("add.rn.f32x2 %0, %0, %1;" : "+l"(d) : "l"(a));
}
__device__ __forceinline__ float lo2(unsigned long long u){ return __uint_as_float((unsigned)(u & 0xffffffffull)); }
__device__ __forceinline__ float hi2(unsigned long long u){ return __uint_as_float((unsigned)(u >> 32)); }
__device__ __forceinline__ bool better(float v,int i,float V,int I){ return (v>V)||(v==V && i<I); }
__device__ __forceinline__ void pfL2(const void* p){
    asm volatile("prefetch.global.L2 [%0];" :: "l"(p));
}

__global__ __launch_bounds__(NTHREAD,1) void k1(
    const float* __restrict__ emb, const float* __restrict__ Wst,
    const float* __restrict__ Wen)
{
    __shared__ __align__(16) float sW[12*HDIM];
    __shared__ float sbuf[NWARP][24];
    __shared__ float sZ[NWARP][TT];
    __shared__ float sT3v[NWARP][TT][3];
    __shared__ int   sT3i[NWARP][TT][3];

    const int tid = threadIdx.x, w = tid>>5, lane = tid&31;

    for(int i=tid;i<HDIM*TT;i+=NTHREAD){
        int h=i/TT, t=i-h*TT;
        sW[t*HDIM+h]      = Wst[i];
        sW[(TT+t)*HDIM+h] = Wen[i];
    }
    __syncthreads();

    unsigned long long pool[12];
    #pragma unroll
    for(int i=0;i<12;i++) pool[i]=0ull;
    float zv=0.f;
    float v0=-3.4e38f,v1=-3.4e38f,v2=-3.4e38f;
    int i0=0x7fffffff,i1=0x7fffffff,i2=0x7fffffff;

    const int b4=(lane>>4)&1, b3=(lane>>3)&1, b2=(lane>>2)&1, b1=(lane>>1)&1, b0=lane&1;
    const int rowown = b4*2+b3;
    const int down   = b2*6 + b1*3 + (b0?2:0);

    const int gw = blockIdx.x*NWARP + w;
    const int nw = GRID1*NWARP;

    const float* bp0 = emb + (size_t)gw*(4*HDIM) + (lane<<2);
    ulonglong2 C0 = *(const ulonglong2*)(bp0);
    ulonglong2 C1 = *(const ulonglong2*)(bp0+HDIM);
    ulonglong2 C2 = *(const ulonglong2*)(bp0+2*HDIM);
    ulonglong2 C3 = *(const ulonglong2*)(bp0+3*HDIM);

    for(int g=gw; g<GROUPS; g+=nw){
        const int r0=g*4;
        const float* cb = emb + (size_t)g*(4*HDIM) + (lane<<2);
        const int gn = (g+nw<GROUPS)? g+nw : g;
        const float* nb0 = emb + (size_t)gn*(4*HDIM) + (lane<<2);

        // L2-prefetch next group's j=1..5 chunks (j=0 is register-prefetched)
        #pragma unroll
        for(int j=1;j<6;j++){
            #pragma unroll
            for(int r=0;r<4;r++) pfL2(nb0 + r*HDIM + j*128);
        }

        unsigned long long a[48];
        #pragma unroll
        for(int i=0;i<48;i++) a[i]=0ull;

        #pragma unroll
        for(int j=0;j<6;j++){
            const float* np = (j<5)? (cb + (j+1)*128) : nb0;
            ulonglong2 N0=*(const ulonglong2*)(np);
            ulonglong2 N1=*(const ulonglong2*)(np+HDIM);
            ulonglong2 N2=*(const ulonglong2*)(np+2*HDIM);
            ulonglong2 N3=*(const ulonglong2*)(np+3*HDIM);

            add2(pool[2*j],  C0.x); add2(pool[2*j],  C1.x); add2(pool[2*j],  C2.x); add2(pool[2*j],  C3.x);
            add2(pool[2*j+1],C0.y); add2(pool[2*j+1],C1.y); add2(pool[2*j+1],C2.y); add2(pool[2*j+1],C3.y);

            const float* wp = sW + j*128 + (lane<<2);
            #pragma unroll
            for(int d=0;d<12;d++){
                ulonglong2 Wv=*(const ulonglong2*)(wp + d*HDIM);
                fma2(a[d],    C0.x,Wv.x); fma2(a[d],    C0.y,Wv.y);
                fma2(a[12+d], C1.x,Wv.x); fma2(a[12+d], C1.y,Wv.y);
                fma2(a[24+d], C2.x,Wv.x); fma2(a[24+d], C2.y,Wv.y);
                fma2(a[36+d], C3.x,Wv.x); fma2(a[36+d], C3.y,Wv.y);
            }
            C0=N0; C1=N1; C2=N2; C3=N3;
        }

        float v[48];
        #pragma unroll
        for(int i=0;i<48;i++) v[i]=lo2(a[i])+hi2(a[i]);

        #pragma unroll
        for(int i=0;i<24;i++){ float s=b4? v[i]:v[i+24]; float r=__shfl_xor_sync(0xffffffffu,s,16); v[i]=(b4? v[i+24]:v[i])+r; }
        #pragma unroll
        for(int i=0;i<12;i++){ float s=b3? v[i]:v[i+12]; float r=__shfl_xor_sync(0xffffffffu,s,8);  v[i]=(b3? v[i+12]:v[i])+r; }
        #pragma unroll
        for(int i=0;i<6;i++){  float s=b2? v[i]:v[i+6];  float r=__shfl_xor_sync(0xffffffffu,s,4);  v[i]=(b2? v[i+6]:v[i])+r; }
        #pragma unroll
        for(int i=0;i<3;i++){  float s=b1? v[i]:v[i+3];  float r=__shfl_xor_sync(0xffffffffu,s,2);  v[i]=(b1? v[i+3]:v[i])+r; }
        {
            float s =b0? v[0]:v[2]; float r =__shfl_xor_sync(0xffffffffu,s,1);
            float s2=v[1];          float r2=__shfl_xor_sync(0xffffffffu,s2,1);
            v[0]=(b0? v[2]:v[0])+r;
            v[1]=v[1]+r2;
        }

        if(down<6){
            sbuf[w][rowown*6+down]=v[0];
            if(!b0) sbuf[w][rowown*6+down+1]=v[1];
        } else {
            const int s=r0+rowown;
            g_end[s*8+(down-6)]=v[0];
            if(!b0) g_end[s*8+(down-5)]=v[1];
        }
        __syncwarp();
        if(lane<TT){
            #pragma unroll
            for(int r=0;r<4;r++){
                float x=sbuf[w][r*6+lane];
                zv += __expf(x);
                const int idx=r0+r;
                if     (better(x,idx,v0,i0)){ v2=v1;i2=i1; v1=v0;i1=i0; v0=x;i0=idx; }
                else if(better(x,idx,v1,i1)){ v2=v1;i2=i1; v1=x; i1=idx; }
                else if(better(x,idx,v2,i2)){ v2=x; i2=idx; }
            }
        }
        __syncwarp();
    }

    if(lane<TT){
        sZ[w][lane]=zv;
        sT3v[w][lane][0]=v0; sT3v[w][lane][1]=v1; sT3v[w][lane][2]=v2;
        sT3i[w][lane][0]=i0; sT3i[w][lane][1]=i1; sT3i[w][lane][2]=i2;
    }
    __syncthreads();
    float* sP = sW;
    #pragma unroll
    for(int j=0;j<6;j++){
        ulonglong2 u; u.x=pool[2*j]; u.y=pool[2*j+1];
        *reinterpret_cast<ulonglong2*>(sP + w*HDIM + j*128 + (lane<<2)) = u;
    }
    __syncthreads();

    for(int h=tid;h<HDIM;h+=NTHREAD){
        float s=0.f;
        #pragma unroll
        for(int ww=0;ww<NWARP;ww++) s+=sP[ww*HDIM+h];
        g_pool[blockIdx.x*HDIM+h]=s;
    }

    if(tid<TT){
        float Z=0.f;
        #pragma unroll
        for(int ww=0;ww<NWARP;ww++) Z+=sZ[ww][tid];
        g_z[blockIdx.x*TT+tid]=Z;

        float V0=-3.4e38f,V1=-3.4e38f,V2=-3.4e38f;
        int   I0=0x7fffffff,I1=0x7fffffff,I2=0x7fffffff;
        #pragma unroll
        for(int ww=0;ww<NWARP;ww++){
            #pragma unroll
            for(int k=0;k<3;k++){
                float x=sT3v[ww][tid][k]; int idx=sT3i[ww][tid][k];
                if     (better(x,idx,V0,I0)){ V2=V1;I2=I1; V1=V0;I1=I0; V0=x;I0=idx; }
                else if(better(x,idx,V1,I1)){ V2=V1;I2=I1; V1=x; I1=idx; }
                else if(better(x,idx,V2,I2)){ V2=x; I2=idx; }
            }
        }
        const int bo=(blockIdx.x*TT+tid)*3;
        g_t3v[bo  ]=V0; g_t3v[bo+1]=V1; g_t3v[bo+2]=V2;
        g_t3i[bo  ]=I0; g_t3i[bo+1]=I1; g_t3i[bo+2]=I2;
    }
}

// ---- k2a: distributed pooled reduction + W1 GEMV partials (64 blocks, 12 h each) ----
__global__ __launch_bounds__(NTHREAD) void k2a(const float* __restrict__ W1)
{
    __shared__ float red[21][12];
    __shared__ float pp[12];
    const int tid=threadIdx.x;
    const int h0=blockIdx.x*12;

    if(tid<252){
        const int hl=tid%12, slice=tid/12;   // 21 slices
        float s=0.f;
        for(int b=slice;b<GRID1;b+=21) s += g_pool[b*HDIM + h0 + hl];
        red[slice][hl]=s;
    }
    __syncthreads();
    if(tid<12){
        float s=0.f;
        #pragma unroll
        for(int i=0;i<21;i++) s+=red[i][tid];
        pp[tid]=s*(1.f/(float)S_TOK);
    }
    __syncthreads();
    if(tid<64){
        float y=0.f;
        #pragma unroll
        for(int h=0;h<12;h++) y += pp[h]*W1[(h0+h)*64+tid];
        g_y[blockIdx.x*64+tid]=y;
    }
}

#define INS3(x,id) do{ \
    if     (better((x),(id),m0,j0)){ m2=m1;j2=j1; m1=m0;j1=j0; m0=(x);j0=(id); } \
    else if(better((x),(id),m1,j1)){ m2=m1;j2=j1; m1=(x);j1=(id); } \
    else if(better((x),(id),m2,j2)){ m2=(x);j2=(id); } }while(0)

// ---- k2b: final merge + MLP + windows (1 block) ----
__global__ __launch_bounds__(NTHREAD) void k2b(
    const float* __restrict__ b1, const float* __restrict__ W2,
    const float* __restrict__ b2, float* __restrict__ out, int out_size)
{
    __shared__ float yred[NTHREAD];
    __shared__ float hbuf[64];
    __shared__ float tc[TT], fZ[TT], fV[TT][3];
    __shared__ int   fI[TT][3];

    const int tid=threadIdx.x, w=tid>>5, lane=tid&31;

    // phase 1: everyone helps reduce y partials (64 blocks -> 4 slices of 16)
    {
        const int u=tid&63, sl=tid>>6;
        float s=0.f;
        #pragma unroll
        for(int i=0;i<16;i++) s += g_y[(sl*16+i)*64 + u];
        yred[tid]=s;
    }
    __syncthreads();

    // phase 2: warps 0-1 do gelu; warps 2-7 do per-type merges
    if(tid<64){
        float aa=yred[tid]+yred[tid+64]+yred[tid+128]+yred[tid+192]+b1[tid];
        hbuf[tid]=0.5f*aa*(1.f+erff(aa*0.70710678118654752f));
    } else if(w>=2){
        const int t=w-2;
        float Z=0.f;
        float m0=-3.4e38f,m1=-3.4e38f,m2=-3.4e38f;
        int   j0=0x7fffffff,j1=0x7fffffff,j2=0x7fffffff;
        for(int b=lane;b<GRID1;b+=32){
            Z += g_z[b*TT+t];
            #pragma unroll
            for(int k=0;k<3;k++){
                float x=g_t3v[(b*TT+t)*3+k]; int id=g_t3i[(b*TT+t)*3+k];
                INS3(x,id);
            }
        }
        #pragma unroll
        for(int off=16;off>0;off>>=1){
            Z += __shfl_xor_sync(0xffffffffu,Z,off);
            float u0=__shfl_xor_sync(0xffffffffu,m0,off); int q0=__shfl_xor_sync(0xffffffffu,j0,off);
            float u1=__shfl_xor_sync(0xffffffffu,m1,off); int q1=__shfl_xor_sync(0xffffffffu,j1,off);
            float u2=__shfl_xor_sync(0xffffffffu,m2,off); int q2=__shfl_xor_sync(0xffffffffu,j2,off);
            INS3(u0,q0); INS3(u1,q1); INS3(u2,q2);
        }
        if(lane==0){
            fZ[t]=Z;
            fV[t][0]=m0; fV[t][1]=m1; fV[t][2]=m2;
            fI[t][0]=j0; fI[t][1]=j1; fI[t][2]=j2;
        }
    }
    __syncthreads();

    if(tid<TT){
        float z=b2[tid];
        #pragma unroll
        for(int j=0;j<64;j++) z+=hbuf[j]*W2[j*TT+tid];
        tc[tid]=1.f/(1.f+expf(-z));
    }
    __syncthreads();

    if(tid<TT*KK){
        const int t=tid/KK, k=tid-t*KK;
        const int idx=fI[t][k];
        const float p=__expf(fV[t][k])/fZ[t];

        float best=-3.4e38f; int off=0;
        #pragma unroll
        for(int wv=0;wv<WIN;wv++){
            int pos=idx+wv;
            if(pos<S_TOK){
                float e=g_end[pos*8+t];
                if(e>best){ best=e; off=wv; }
            }
        }
        const bool valid=(tc[t]>=0.3f)&&(p>=0.15f);
        const float c=valid? p*tc[t] : 0.f;
        const int base=t*KK+k;
        if(base      < out_size) out[base]      = c;
        if(18+base   < out_size) out[18+base]   = (float)idx;
        if(36+base   < out_size) out[36+base]   = (float)(idx+off+1);
        if(54+base   < out_size) out[54+base]   = valid? 1.f:0.f;
    }
}

extern "C" void kernel_launch(void* const* d_in, const int* in_sizes, int n_in,
                              void* d_out, int out_size)
{
    const float* emb = (const float*)d_in[0];
    const float* Wst = (const float*)d_in[1];
    const float* Wen = (const float*)d_in[3];
    const float* W1  = (const float*)d_in[5];
    const float* b1  = (const float*)d_in[6];
    const float* W2  = (const float*)d_in[7];
    const float* b2  = (const float*)d_in[8];

    k1 <<<GRID1, NTHREAD>>>(emb, Wst, Wen);
    k2a<<<GRID2A, NTHREAD>>>(W1);
    k2b<<<1, NTHREAD>>>(b1, W2, b2, (float*)d_out, out_size);
}